// round 5
// baseline (speedup 1.0000x reference)
#include <cuda_runtime.h>
#include <cstdint>

// TVLoss: circular-gradient magnitude mean (== reference's FFT path).
//   gx[i,j] = f[i,j] - f[i,(j+1)%W]
//   gy[i,j] = f[i,j] - f[(i+1)%H,j]
//   out = mean( sqrt(gx^2 + gy^2) )
//
// R5: exactly-one-resident-wave grid (1536 blocks x 128thr, <=42 regs so all
// blocks co-resident on 148 SMs), KROWS=32 strips (3.1% overlap traffic),
// 2-row software pipeline for MLP, fused last-block reduction.

static constexpr int B = 32, C = 3, H = 512, W = 512;
static constexpr long long TOTAL = (long long)B * C * H * W;   // 25,165,824
static constexpr int PLANES = B * C;                           // 96
static constexpr int W4     = W / 4;                           // 128 float4/row
static constexpr int KROWS  = 32;                              // strip height
static constexpr int STRIPS = H / KROWS;                       // 16 per plane
static constexpr int NTHR   = 128;                             // one strip/block
static constexpr int NBLK   = PLANES * STRIPS;                 // 1536

__device__ float    g_partials[NBLK];
__device__ unsigned g_count = 0;

__device__ __forceinline__ float fsqrt_approx(float x) {
    float r;
    asm("sqrt.approx.f32 %0, %1;" : "=f"(r) : "f"(x));
    return r;
}

__global__ __launch_bounds__(NTHR, 12)
void tv_fused(const float4* __restrict__ in4, float* __restrict__ out) {
    const float* __restrict__ inf = (const float*)in4;

    const int tid  = threadIdx.x;
    const int c4   = tid;                          // column, float4 units (0..127)
    const int sid  = blockIdx.x;                   // strip id
    const int pl   = sid >> 4;                     // plane (0..95)
    const int st   = sid & (STRIPS - 1);           // strip within plane
    const int row0 = st << 5;                      // first row of strip

    const int planeBase = pl << 16;                // plane * 512 rows * 128 f4
    const int lane = tid & 31;
    const int rc4  = (c4 + 1) & (W4 - 1);          // right-neighbor column

    float acc = 0.0f;

    float4 s = in4[planeBase + (row0 << 7) + c4];

    #pragma unroll
    for (int k = 0; k < KROWS; k += 2) {
        const int n1 = (row0 + k + 1) & (H - 1);   // wrap only on last row of plane
        const int n2 = (row0 + k + 2) & (H - 1);
        const float4 d1 = in4[planeBase + (n1 << 7) + c4];  // independent
        const float4 d2 = in4[planeBase + (n2 << 7) + c4];  // independent

        // ── row row0+k : (s, d1) ──
        {
            const int row = row0 + k;
            float rn = __shfl_down_sync(0xFFFFFFFFu, s.x, 1);
            if (lane == 31)
                rn = inf[(planeBase << 2) + (row << 9) + (rc4 << 2)];
            const float dx0 = s.x - s.y, dx1 = s.y - s.z;
            const float dx2 = s.z - s.w, dx3 = s.w - rn;
            const float dy0 = s.x - d1.x, dy1 = s.y - d1.y;
            const float dy2 = s.z - d1.z, dy3 = s.w - d1.w;
            acc += fsqrt_approx(fmaf(dx0, dx0, dy0 * dy0));
            acc += fsqrt_approx(fmaf(dx1, dx1, dy1 * dy1));
            acc += fsqrt_approx(fmaf(dx2, dx2, dy2 * dy2));
            acc += fsqrt_approx(fmaf(dx3, dx3, dy3 * dy3));
        }
        // ── row row0+k+1 : (d1, d2) ──
        {
            const int row = row0 + k + 1;
            float rn = __shfl_down_sync(0xFFFFFFFFu, d1.x, 1);
            if (lane == 31)
                rn = inf[(planeBase << 2) + (row << 9) + (rc4 << 2)];
            const float dx0 = d1.x - d1.y, dx1 = d1.y - d1.z;
            const float dx2 = d1.z - d1.w, dx3 = d1.w - rn;
            const float dy0 = d1.x - d2.x, dy1 = d1.y - d2.y;
            const float dy2 = d1.z - d2.z, dy3 = d1.w - d2.w;
            acc += fsqrt_approx(fmaf(dx0, dx0, dy0 * dy0));
            acc += fsqrt_approx(fmaf(dx1, dx1, dy1 * dy1));
            acc += fsqrt_approx(fmaf(dx2, dx2, dy2 * dy2));
            acc += fsqrt_approx(fmaf(dx3, dx3, dy3 * dy3));
        }
        s = d2;
    }

    // ── block reduce (4 warps) ──
    #pragma unroll
    for (int o = 16; o; o >>= 1) acc += __shfl_xor_sync(0xFFFFFFFFu, acc, o);

    __shared__ float smem[NTHR / 32];
    if (lane == 0) smem[tid >> 5] = acc;
    __syncthreads();

    if (tid < 32) {
        float v = (tid < NTHR / 32) ? smem[tid] : 0.0f;
        #pragma unroll
        for (int o = 2; o; o >>= 1) v += __shfl_xor_sync(0xFFFFFFFFu, v, o);
        if (tid == 0) g_partials[blockIdx.x] = v;
    }

    // ── last-block final reduction ──
    __shared__ bool amLast;
    if (tid == 0) {
        __threadfence();
        unsigned prev = atomicAdd(&g_count, 1u);
        amLast = (prev == (unsigned)(NBLK - 1));
    }
    __syncthreads();

    if (amLast) {
        float v = 0.0f;
        for (int i = tid; i < NBLK; i += NTHR) v += g_partials[i];
        #pragma unroll
        for (int o = 16; o; o >>= 1) v += __shfl_xor_sync(0xFFFFFFFFu, v, o);

        __shared__ float sm2[NTHR / 32];
        if (lane == 0) sm2[tid >> 5] = v;
        __syncthreads();
        if (tid < 32) {
            float w = (tid < NTHR / 32) ? sm2[tid] : 0.0f;
            #pragma unroll
            for (int o = 2; o; o >>= 1) w += __shfl_xor_sync(0xFFFFFFFFu, w, o);
            if (tid == 0) {
                out[0] = w / (float)TOTAL;
                g_count = 0;                       // reset for next graph replay
            }
        }
    }
}

extern "C" void kernel_launch(void* const* d_in, const int* in_sizes, int n_in,
                              void* d_out, int out_size) {
    tv_fused<<<NBLK, NTHR>>>((const float4*)d_in[0], (float*)d_out);
}

// round 6
// speedup vs baseline: 1.0218x; 1.0218x over previous
#include <cuda_runtime.h>
#include <cstdint>

// TVLoss: circular-gradient magnitude mean (== reference's FFT path).
//   gx[i,j] = f[i,j] - f[i,(j+1)%W]
//   gy[i,j] = f[i,j] - f[(i+1)%H,j]
//   out = mean( sqrt(gx^2 + gy^2) )
//
// R6: 256thr blocks (high warp count -> chip-wide MLP), 2 strips of KROWS=32
// per block (3.1% overlap traffic), 4-row software pipeline (4 independent
// LDG.128 in flight per thread), fused last-block reduction.

static constexpr int B = 32, C = 3, H = 512, W = 512;
static constexpr long long TOTAL = (long long)B * C * H * W;   // 25,165,824
static constexpr int PLANES = B * C;                           // 96
static constexpr int W4     = W / 4;                           // 128 float4/row
static constexpr int KROWS  = 32;                              // strip height
static constexpr int STRIPS = H / KROWS;                       // 16 per plane
static constexpr int NTHR   = 256;                             // 2 strips/block
static constexpr int NBLK   = PLANES * STRIPS / 2;             // 768

__device__ float    g_partials[NBLK];
__device__ unsigned g_count = 0;

__device__ __forceinline__ float fsqrt_approx(float x) {
    float r;
    asm("sqrt.approx.f32 %0, %1;" : "=f"(r) : "f"(x));
    return r;
}

// Process one row: self-vec s, down-vec d, right-neighbor rn (scalar).
__device__ __forceinline__ float row_mag(const float4 s, const float4 d, const float rn) {
    const float dx0 = s.x - s.y, dx1 = s.y - s.z;
    const float dx2 = s.z - s.w, dx3 = s.w - rn;
    const float dy0 = s.x - d.x, dy1 = s.y - d.y;
    const float dy2 = s.z - d.z, dy3 = s.w - d.w;
    float a  = fsqrt_approx(fmaf(dx0, dx0, dy0 * dy0));
    a += fsqrt_approx(fmaf(dx1, dx1, dy1 * dy1));
    a += fsqrt_approx(fmaf(dx2, dx2, dy2 * dy2));
    a += fsqrt_approx(fmaf(dx3, dx3, dy3 * dy3));
    return a;
}

__global__ __launch_bounds__(NTHR, 6)
void tv_fused(const float4* __restrict__ in4, float* __restrict__ out) {
    const float* __restrict__ inf = (const float*)in4;

    const int tid  = threadIdx.x;
    const int c4   = tid & (W4 - 1);               // column (float4 units)
    const int sid  = blockIdx.x * 2 + (tid >> 7);  // global strip id
    const int pl   = sid >> 4;                     // plane (0..95)
    const int st   = sid & (STRIPS - 1);           // strip within plane
    const int row0 = st << 5;                      // first row of strip

    const int planeBase = pl << 16;                // plane * 512 rows * 128 f4
    const int lane = tid & 31;
    const int rc4  = (c4 + 1) & (W4 - 1);          // right-neighbor column

    float acc = 0.0f;

    float4 s = in4[planeBase + (row0 << 7) + c4];

    #pragma unroll
    for (int k = 0; k < KROWS; k += 4) {
        // 4 independent loads, issued back-to-back (MLP=4 per thread)
        const int n1 = (row0 + k + 1) & (H - 1);
        const int n2 = (row0 + k + 2) & (H - 1);
        const int n3 = (row0 + k + 3) & (H - 1);
        const int n4 = (row0 + k + 4) & (H - 1);
        const float4 d1 = in4[planeBase + (n1 << 7) + c4];
        const float4 d2 = in4[planeBase + (n2 << 7) + c4];
        const float4 d3 = in4[planeBase + (n3 << 7) + c4];
        const float4 d4 = in4[planeBase + (n4 << 7) + c4];

        float rn;

        rn = __shfl_down_sync(0xFFFFFFFFu, s.x, 1);
        if (lane == 31) rn = inf[(planeBase << 2) + ((row0 + k) << 9) + (rc4 << 2)];
        acc += row_mag(s, d1, rn);

        rn = __shfl_down_sync(0xFFFFFFFFu, d1.x, 1);
        if (lane == 31) rn = inf[(planeBase << 2) + ((row0 + k + 1) << 9) + (rc4 << 2)];
        acc += row_mag(d1, d2, rn);

        rn = __shfl_down_sync(0xFFFFFFFFu, d2.x, 1);
        if (lane == 31) rn = inf[(planeBase << 2) + ((row0 + k + 2) << 9) + (rc4 << 2)];
        acc += row_mag(d2, d3, rn);

        rn = __shfl_down_sync(0xFFFFFFFFu, d3.x, 1);
        if (lane == 31) rn = inf[(planeBase << 2) + ((row0 + k + 3) << 9) + (rc4 << 2)];
        acc += row_mag(d3, d4, rn);

        s = d4;
    }

    // ── block reduce (8 warps) ──
    #pragma unroll
    for (int o = 16; o; o >>= 1) acc += __shfl_xor_sync(0xFFFFFFFFu, acc, o);

    __shared__ float smem[NTHR / 32];
    if (lane == 0) smem[tid >> 5] = acc;
    __syncthreads();

    if (tid < 32) {
        float v = (tid < NTHR / 32) ? smem[tid] : 0.0f;
        #pragma unroll
        for (int o = 4; o; o >>= 1) v += __shfl_xor_sync(0xFFFFFFFFu, v, o);
        if (tid == 0) g_partials[blockIdx.x] = v;
    }

    // ── last-block final reduction ──
    __shared__ bool amLast;
    if (tid == 0) {
        __threadfence();
        unsigned prev = atomicAdd(&g_count, 1u);
        amLast = (prev == (unsigned)(NBLK - 1));
    }
    __syncthreads();

    if (amLast) {
        float v = 0.0f;
        for (int i = tid; i < NBLK; i += NTHR) v += g_partials[i];
        #pragma unroll
        for (int o = 16; o; o >>= 1) v += __shfl_xor_sync(0xFFFFFFFFu, v, o);

        __shared__ float sm2[NTHR / 32];
        if (lane == 0) sm2[tid >> 5] = v;
        __syncthreads();
        if (tid < 32) {
            float w = (tid < NTHR / 32) ? sm2[tid] : 0.0f;
            #pragma unroll
            for (int o = 4; o; o >>= 1) w += __shfl_xor_sync(0xFFFFFFFFu, w, o);
            if (tid == 0) {
                out[0] = w / (float)TOTAL;
                g_count = 0;                       // reset for next graph replay
            }
        }
    }
}

extern "C" void kernel_launch(void* const* d_in, const int* in_sizes, int n_in,
                              void* d_out, int out_size) {
    tv_fused<<<NBLK, NTHR>>>((const float4*)d_in[0], (float*)d_out);
}